// round 2
// baseline (speedup 1.0000x reference)
#include <cuda_runtime.h>
#include <math.h>

#define NNODES_MAX 100000
#define EDGES_MAX  3200000

// ---- static scratch (no allocations allowed) ----
__device__ int   g_cnt[NNODES_MAX];
__device__ int   g_cursor[NNODES_MAX];
__device__ int   g_rowptr[NNODES_MAX + 1];
__device__ float g_dinv[NNODES_MAX];
__device__ int2  g_edges[EDGES_MAX];                       // (src, norm bits)
__device__ float g_xin[(size_t)NNODES_MAX * 65];
__device__ float g_hA[(size_t)NNODES_MAX * 256];
__device__ float g_hB[(size_t)NNODES_MAX * 256];

__device__ __forceinline__ float gelu_f(float x) {
    // matches jax.nn.gelu(approximate=True)
    float u = 0.7978845608028654f * (x + 0.044715f * x * x * x);
    return 0.5f * x * (1.0f + tanhf(u));
}

// ---------------- preprocessing ----------------

__global__ void zero_kernel(int n) {
    int i = blockIdx.x * blockDim.x + threadIdx.x;
    if (i < n) { g_cnt[i] = 0; g_cursor[i] = 0; }
}

__global__ void hist_kernel(const int* __restrict__ dst, int E) {
    int i = blockIdx.x * blockDim.x + threadIdx.x;
    if (i < E) atomicAdd(&g_cnt[dst[i]], 1);
}

__global__ void dinv_kernel(int n) {
    int i = blockIdx.x * blockDim.x + threadIdx.x;
    if (i < n) g_dinv[i] = rsqrtf((float)(g_cnt[i] + 1));  // +1 self loop
}

// single-block exclusive scan of g_cnt -> g_rowptr (n up to 100000)
__global__ void scan_kernel(int n) {
    __shared__ int warpsums[32];
    __shared__ int s_carry;
    int tid = threadIdx.x, lane = tid & 31, wid = tid >> 5;
    if (tid == 0) s_carry = 0;
    __syncthreads();
    for (int base = 0; base < n; base += 1024) {
        int i = base + tid;
        int v = (i < n) ? g_cnt[i] : 0;
        int x = v;
        #pragma unroll
        for (int off = 1; off < 32; off <<= 1) {
            int t = __shfl_up_sync(0xffffffffu, x, off);
            if (lane >= off) x += t;
        }
        if (lane == 31) warpsums[wid] = x;
        __syncthreads();
        if (wid == 0) {
            int w = warpsums[lane];
            #pragma unroll
            for (int off = 1; off < 32; off <<= 1) {
                int t = __shfl_up_sync(0xffffffffu, w, off);
                if (lane >= off) w += t;
            }
            warpsums[lane] = w;
        }
        __syncthreads();
        int warpoff = (wid > 0) ? warpsums[wid - 1] : 0;
        if (i < n) g_rowptr[i] = s_carry + warpoff + x - v;
        __syncthreads();
        if (tid == 0) s_carry += warpsums[31];
        __syncthreads();
    }
    if (threadIdx.x == 0) g_rowptr[n] = s_carry;
}

__global__ void fill_kernel(const int* __restrict__ src,
                            const int* __restrict__ dst, int E) {
    int i = blockIdx.x * blockDim.x + threadIdx.x;
    if (i < E) {
        int s = src[i];
        int d = dst[i];
        int pos = g_rowptr[d] + atomicAdd(&g_cursor[d], 1);
        g_edges[pos] = make_int2(s, __float_as_int(g_dinv[s] * g_dinv[d]));
    }
}

__global__ void concat_kernel(const float* __restrict__ x, const float* __restrict__ t, int n) {
    int total = n * 65;
    int i = blockIdx.x * blockDim.x + threadIdx.x;
    if (i < total) {
        int row = i / 65;
        int c = i - row * 65;
        g_xin[i] = (c < 64) ? x[(size_t)row * 64 + c] : t[row];
    }
}

// ---------------- GEMM ----------------
// C[M,N] = A[M,K] @ W[K,N]  (+ optional bias / gelu)
// block tile 128x64, 256 threads, thread tile 8x4, K chunk 16.
// mode: 0 = none, 1 = bias+gelu, 2 = bias only
__global__ void gemm_kernel(const float* __restrict__ A, const float* __restrict__ W,
                            const float* __restrict__ bias, float* __restrict__ C,
                            int M, int K, int N, int mode) {
    __shared__ float As[16][128];
    __shared__ float Ws[16][64];

    int m0 = blockIdx.x * 128;
    int n0 = blockIdx.y * 64;
    int tid = threadIdx.x;
    int tx = tid % 16;       // col group (4 cols)
    int ty = tid / 16;       // row group (rows ty + 16*i)

    float acc[8][4];
    #pragma unroll
    for (int i = 0; i < 8; i++)
        #pragma unroll
        for (int j = 0; j < 4; j++) acc[i][j] = 0.0f;

    int a_row = tid / 2;             // m within tile
    int a_k0  = (tid % 2) * 8;       // 8 consecutive k's
    int w_k   = tid / 16;
    int w_n   = (tid % 16) * 4;

    for (int kc = 0; kc < K; kc += 16) {
        // load A tile
        int gm = m0 + a_row;
        #pragma unroll
        for (int j = 0; j < 8; j++) {
            int gk = kc + a_k0 + j;
            float v = 0.0f;
            if (gm < M && gk < K) v = A[(size_t)gm * K + gk];
            As[a_k0 + j][a_row] = v;
        }
        // load W tile (float4)
        {
            float4 wv = make_float4(0.f, 0.f, 0.f, 0.f);
            int gk = kc + w_k;
            if (gk < K) wv = *(const float4*)&W[(size_t)gk * N + n0 + w_n];
            *(float4*)&Ws[w_k][w_n] = wv;
        }
        __syncthreads();

        #pragma unroll
        for (int k = 0; k < 16; k++) {
            float4 wv = *(const float4*)&Ws[k][tx * 4];
            #pragma unroll
            for (int i = 0; i < 8; i++) {
                float a = As[k][ty + 16 * i];
                acc[i][0] = fmaf(a, wv.x, acc[i][0]);
                acc[i][1] = fmaf(a, wv.y, acc[i][1]);
                acc[i][2] = fmaf(a, wv.z, acc[i][2]);
                acc[i][3] = fmaf(a, wv.w, acc[i][3]);
            }
        }
        __syncthreads();
    }

    #pragma unroll
    for (int i = 0; i < 8; i++) {
        int gm = m0 + ty + 16 * i;
        if (gm < M) {
            #pragma unroll
            for (int j = 0; j < 4; j++) {
                int gn = n0 + tx * 4 + j;
                float v = acc[i][j];
                if (mode != 0) v += bias[gn];
                if (mode == 1) v = gelu_f(v);
                C[(size_t)gm * N + gn] = v;
            }
        }
    }
}

// ---------------- aggregation (warp per node, CSR, no atomics) ----------------
// out[i] = gelu( sum_{(s->i)} norm * h[s] + dinv[i]^2 * h[i] + bias )
template <int R>   // d = 32*R
__global__ void agg_kernel(const float* __restrict__ h, const float* __restrict__ bias,
                           float* __restrict__ out, int n) {
    int warp = (blockIdx.x * blockDim.x + threadIdx.x) >> 5;
    int lane = threadIdx.x & 31;
    if (warp >= n) return;
    const int d = 32 * R;

    float acc[R];
    #pragma unroll
    for (int r = 0; r < R; r++) acc[r] = 0.0f;

    int beg = g_rowptr[warp];
    int end = g_rowptr[warp + 1];
    for (int base = beg; base < end; base += 32) {
        int2 ed = make_int2(0, 0);
        if (base + lane < end) ed = g_edges[base + lane];
        int cnt = min(32, end - base);
        for (int j = 0; j < cnt; j++) {
            int s   = __shfl_sync(0xffffffffu, ed.x, j);
            float w = __int_as_float(__shfl_sync(0xffffffffu, ed.y, j));
            const float* hr = h + (size_t)s * d + lane;
            #pragma unroll
            for (int r = 0; r < R; r++)
                acc[r] = fmaf(w, __ldg(hr + 32 * r), acc[r]);
        }
    }
    // self loop
    float di = g_dinv[warp];
    float ws = di * di;
    const float* hs = h + (size_t)warp * d + lane;
    #pragma unroll
    for (int r = 0; r < R; r++)
        acc[r] = fmaf(ws, hs[32 * r], acc[r]);

    float* op = out + (size_t)warp * d + lane;
    #pragma unroll
    for (int r = 0; r < R; r++) {
        float v = acc[r] + bias[lane + 32 * r];
        op[32 * r] = gelu_f(v);
    }
}

// ---------------- launch ----------------

static inline void launch_gemm(const float* A, const float* W, const float* bias,
                               float* C, int M, int K, int N, int mode) {
    dim3 grid((M + 127) / 128, N / 64);
    gemm_kernel<<<grid, 256>>>(A, W, bias, C, M, K, N, mode);
}

extern "C" void kernel_launch(void* const* d_in, const int* in_sizes, int n_in,
                              void* d_out, int out_size) {
    const float* x  = (const float*)d_in[0];
    const float* t  = (const float*)d_in[1];
    const int*   ei = (const int*)d_in[2];           // int32! (JAX x64 disabled)
    const float* W1 = (const float*)d_in[3];  const float* b1 = (const float*)d_in[4];
    const float* W2 = (const float*)d_in[5];  const float* b2 = (const float*)d_in[6];
    const float* W3 = (const float*)d_in[7];  const float* b3 = (const float*)d_in[8];
    const float* W4 = (const float*)d_in[9];  const float* b4 = (const float*)d_in[10];
    const float* F1 = (const float*)d_in[11]; const float* c1 = (const float*)d_in[12];
    const float* F2 = (const float*)d_in[13]; const float* c2 = (const float*)d_in[14];
    const float* F3 = (const float*)d_in[15]; const float* c3 = (const float*)d_in[16];
    float* out = (float*)d_out;

    int n = in_sizes[1];              // N nodes (t has N elements)
    int E = in_sizes[2] / 2;          // edge_index is [2, E]
    if (n > NNODES_MAX) n = NNODES_MAX;
    if (E > EDGES_MAX)  E = EDGES_MAX;

    const int* src32 = ei;
    const int* dst32 = ei + E;

    float *hA, *hB, *xin;
    cudaGetSymbolAddress((void**)&hA,  g_hA);
    cudaGetSymbolAddress((void**)&hB,  g_hB);
    cudaGetSymbolAddress((void**)&xin, g_xin);

    int nb = (n + 255) / 256;
    int eb = (E + 255) / 256;

    // --- graph preprocessing (CSR by dst + norms) ---
    zero_kernel<<<nb, 256>>>(n);
    hist_kernel<<<eb, 256>>>(dst32, E);
    dinv_kernel<<<nb, 256>>>(n);
    scan_kernel<<<1, 1024>>>(n);
    fill_kernel<<<eb, 256>>>(src32, dst32, E);
    concat_kernel<<<(n * 65 + 255) / 256, 256>>>(x, t, n);

    int aggBlocks = (n * 32 + 255) / 256;   // warp per node, 8 warps/block

    // --- GCN layer 1: [N,65]@[65,64] -> agg(64) ---
    launch_gemm(xin, W1, nullptr, hA, n, 65, 64, 0);
    agg_kernel<2><<<aggBlocks, 256>>>(hA, b1, hB, n);

    // --- GCN layer 2: [N,64]@[64,128] -> agg(128) ---
    launch_gemm(hB, W2, nullptr, hA, n, 64, 128, 0);
    agg_kernel<4><<<aggBlocks, 256>>>(hA, b2, hB, n);

    // --- GCN layer 3: [N,128]@[128,256] -> agg(256) ---
    launch_gemm(hB, W3, nullptr, hA, n, 128, 256, 0);
    agg_kernel<8><<<aggBlocks, 256>>>(hA, b3, hB, n);

    // --- GCN layer 4: [N,256]@[256,128] -> agg(128) ---
    launch_gemm(hB, W4, nullptr, hA, n, 256, 128, 0);
    agg_kernel<4><<<aggBlocks, 256>>>(hA, b4, hB, n);

    // --- MLP head ---
    launch_gemm(hB, F1, c1, hA, n, 128, 256, 1);   // bias+gelu
    launch_gemm(hA, F2, c2, hB, n, 256, 128, 1);   // bias+gelu
    launch_gemm(hB, F3, c3, out, n, 128, 64, 2);   // bias only
}

// round 3
// speedup vs baseline: 1.1675x; 1.1675x over previous
#include <cuda_runtime.h>
#include <math.h>

#define NNODES_MAX 100000
#define EDGES_MAX  3200000
#define SCAN_BLK   1024
#define MAX_SBLOCKS 128   // ceil(100000/1024) = 98

// ---- static scratch (no allocations allowed) ----
__device__ int   g_cnt[NNODES_MAX];
__device__ int   g_cursor[NNODES_MAX];
__device__ int   g_rowptr[NNODES_MAX + 1];
__device__ int   g_bsum[MAX_SBLOCKS];
__device__ float g_dinv[NNODES_MAX];
__device__ int2  g_edges[EDGES_MAX];                       // (src, norm bits)
__device__ float g_xin[(size_t)NNODES_MAX * 65];
__device__ float g_hA[(size_t)NNODES_MAX * 256];
__device__ float g_hB[(size_t)NNODES_MAX * 256];

__device__ __forceinline__ float gelu_f(float x) {
    // matches jax.nn.gelu(approximate=True)
    float u = 0.7978845608028654f * (x + 0.044715f * x * x * x);
    return 0.5f * x * (1.0f + tanhf(u));
}

// ---------------- preprocessing ----------------

__global__ void zero_kernel(int n) {
    int i = blockIdx.x * blockDim.x + threadIdx.x;
    if (i < n) { g_cnt[i] = 0; g_cursor[i] = 0; }
}

__global__ void hist_kernel(const int* __restrict__ dst, int E) {
    int i = blockIdx.x * blockDim.x + threadIdx.x;
    if (i < E) atomicAdd(&g_cnt[dst[i]], 1);
}

__global__ void dinv_kernel(int n) {
    int i = blockIdx.x * blockDim.x + threadIdx.x;
    if (i < n) g_dinv[i] = rsqrtf((float)(g_cnt[i] + 1));  // +1 self loop
}

// ---- multi-block exclusive scan: cnt -> rowptr ----
// phase 1: per-block exclusive scan, block totals to g_bsum
__global__ void scan1_kernel(int n) {
    __shared__ int ws[32];
    int tid = threadIdx.x, lane = tid & 31, wid = tid >> 5;
    int i = blockIdx.x * SCAN_BLK + tid;
    int v = (i < n) ? g_cnt[i] : 0;
    int x = v;
    #pragma unroll
    for (int off = 1; off < 32; off <<= 1) {
        int t = __shfl_up_sync(0xffffffffu, x, off);
        if (lane >= off) x += t;
    }
    if (lane == 31) ws[wid] = x;
    __syncthreads();
    if (wid == 0) {
        int w = ws[lane];
        #pragma unroll
        for (int off = 1; off < 32; off <<= 1) {
            int t = __shfl_up_sync(0xffffffffu, w, off);
            if (lane >= off) w += t;
        }
        ws[lane] = w;
    }
    __syncthreads();
    int woff = (wid > 0) ? ws[wid - 1] : 0;
    if (i < n) g_rowptr[i] = woff + x - v;       // block-local exclusive
    if (tid == 0) g_bsum[blockIdx.x] = ws[31];   // block total
}

// phase 2: exclusive scan of block sums (<=128 entries), one block
__global__ void scan2_kernel(int nb, int n) {
    __shared__ int s[MAX_SBLOCKS];
    int tid = threadIdx.x;
    if (tid < nb) s[tid] = g_bsum[tid];
    __syncthreads();
    if (tid == 0) {
        int run = 0;
        for (int i = 0; i < nb; i++) { int v = s[i]; s[i] = run; run += v; }
        g_rowptr[n] = run;                        // total edge count
    }
    __syncthreads();
    if (tid < nb) g_bsum[tid] = s[tid];
}

// phase 3: add block offsets
__global__ void scan3_kernel(int n) {
    int i = blockIdx.x * SCAN_BLK + threadIdx.x;
    if (i < n) g_rowptr[i] += g_bsum[blockIdx.x];
}

__global__ void fill_kernel(const int* __restrict__ src,
                            const int* __restrict__ dst, int E) {
    int i = blockIdx.x * blockDim.x + threadIdx.x;
    if (i < E) {
        int s = src[i];
        int d = dst[i];
        int pos = g_rowptr[d] + atomicAdd(&g_cursor[d], 1);
        g_edges[pos] = make_int2(s, __float_as_int(g_dinv[s] * g_dinv[d]));
    }
}

__global__ void concat_kernel(const float* __restrict__ x, const float* __restrict__ t, int n) {
    int total = n * 65;
    int i = blockIdx.x * blockDim.x + threadIdx.x;
    if (i < total) {
        int row = i / 65;
        int c = i - row * 65;
        g_xin[i] = (c < 64) ? x[(size_t)row * 64 + c] : t[row];
    }
}

// ---------------- GEMM ----------------
// C[M,N] = A[M,K] @ W[K,N]  (+ optional bias / gelu)
// block tile 128x64, 256 threads, thread tile 8x4, K chunk 16.
// mode: 0 = none, 1 = bias+gelu, 2 = bias only
__global__ void gemm_kernel(const float* __restrict__ A, const float* __restrict__ W,
                            const float* __restrict__ bias, float* __restrict__ C,
                            int M, int K, int N, int mode) {
    __shared__ float As[16][128];
    __shared__ float Ws[16][64];

    int m0 = blockIdx.x * 128;
    int n0 = blockIdx.y * 64;
    int tid = threadIdx.x;
    int tx = tid % 16;       // col group (4 cols)
    int ty = tid / 16;       // row group (rows ty + 16*i)

    float acc[8][4];
    #pragma unroll
    for (int i = 0; i < 8; i++)
        #pragma unroll
        for (int j = 0; j < 4; j++) acc[i][j] = 0.0f;

    int a_row = tid / 2;             // m within tile
    int a_k0  = (tid % 2) * 8;       // 8 consecutive k's
    int w_k   = tid / 16;
    int w_n   = (tid % 16) * 4;

    for (int kc = 0; kc < K; kc += 16) {
        // load A tile
        int gm = m0 + a_row;
        #pragma unroll
        for (int j = 0; j < 8; j++) {
            int gk = kc + a_k0 + j;
            float v = 0.0f;
            if (gm < M && gk < K) v = A[(size_t)gm * K + gk];
            As[a_k0 + j][a_row] = v;
        }
        // load W tile (float4)
        {
            float4 wv = make_float4(0.f, 0.f, 0.f, 0.f);
            int gk = kc + w_k;
            if (gk < K) wv = *(const float4*)&W[(size_t)gk * N + n0 + w_n];
            *(float4*)&Ws[w_k][w_n] = wv;
        }
        __syncthreads();

        #pragma unroll
        for (int k = 0; k < 16; k++) {
            float4 wv = *(const float4*)&Ws[k][tx * 4];
            #pragma unroll
            for (int i = 0; i < 8; i++) {
                float a = As[k][ty + 16 * i];
                acc[i][0] = fmaf(a, wv.x, acc[i][0]);
                acc[i][1] = fmaf(a, wv.y, acc[i][1]);
                acc[i][2] = fmaf(a, wv.z, acc[i][2]);
                acc[i][3] = fmaf(a, wv.w, acc[i][3]);
            }
        }
        __syncthreads();
    }

    #pragma unroll
    for (int i = 0; i < 8; i++) {
        int gm = m0 + ty + 16 * i;
        if (gm < M) {
            #pragma unroll
            for (int j = 0; j < 4; j++) {
                int gn = n0 + tx * 4 + j;
                float v = acc[i][j];
                if (mode != 0) v += bias[gn];
                if (mode == 1) v = gelu_f(v);
                C[(size_t)gm * N + gn] = v;
            }
        }
    }
}

// ---------------- aggregation (warp per node, CSR, no atomics) ----------------
// EPI=true : out[i] = gelu( sum norm*h[s] + dinv_i^2*h[i] + bias )
// EPI=false: out[i] =       sum norm*h[s] + dinv_i^2*h[i]
template <int R, bool EPI>   // d = 32*R
__global__ void agg_kernel(const float* __restrict__ h, const float* __restrict__ bias,
                           float* __restrict__ out, int n) {
    int warp = (blockIdx.x * blockDim.x + threadIdx.x) >> 5;
    int lane = threadIdx.x & 31;
    if (warp >= n) return;
    const int d = 32 * R;

    float acc[R];
    #pragma unroll
    for (int r = 0; r < R; r++) acc[r] = 0.0f;

    int beg = g_rowptr[warp];
    int end = g_rowptr[warp + 1];
    for (int base = beg; base < end; base += 32) {
        int2 ed = make_int2(0, 0);
        if (base + lane < end) ed = g_edges[base + lane];
        int cnt = min(32, end - base);
        for (int j = 0; j < cnt; j++) {
            int s   = __shfl_sync(0xffffffffu, ed.x, j);
            float w = __int_as_float(__shfl_sync(0xffffffffu, ed.y, j));
            const float* hr = h + (size_t)s * d + lane;
            #pragma unroll
            for (int r = 0; r < R; r++)
                acc[r] = fmaf(w, __ldg(hr + 32 * r), acc[r]);
        }
    }
    // self loop
    float di = g_dinv[warp];
    float ws = di * di;
    const float* hs = h + (size_t)warp * d + lane;
    #pragma unroll
    for (int r = 0; r < R; r++)
        acc[r] = fmaf(ws, hs[32 * r], acc[r]);

    float* op = out + (size_t)warp * d + lane;
    #pragma unroll
    for (int r = 0; r < R; r++) {
        float v = acc[r];
        if (EPI) v = gelu_f(v + bias[lane + 32 * r]);
        op[32 * r] = v;
    }
}

// ---------------- launch ----------------

static inline void launch_gemm(const float* A, const float* W, const float* bias,
                               float* C, int M, int K, int N, int mode) {
    dim3 grid((M + 127) / 128, N / 64);
    gemm_kernel<<<grid, 256>>>(A, W, bias, C, M, K, N, mode);
}

extern "C" void kernel_launch(void* const* d_in, const int* in_sizes, int n_in,
                              void* d_out, int out_size) {
    const float* x  = (const float*)d_in[0];
    const float* t  = (const float*)d_in[1];
    const int*   ei = (const int*)d_in[2];           // int32 (JAX x64 disabled)
    const float* W1 = (const float*)d_in[3];  const float* b1 = (const float*)d_in[4];
    const float* W2 = (const float*)d_in[5];  const float* b2 = (const float*)d_in[6];
    const float* W3 = (const float*)d_in[7];  const float* b3 = (const float*)d_in[8];
    const float* W4 = (const float*)d_in[9];  const float* b4 = (const float*)d_in[10];
    const float* F1 = (const float*)d_in[11]; const float* c1 = (const float*)d_in[12];
    const float* F2 = (const float*)d_in[13]; const float* c2 = (const float*)d_in[14];
    const float* F3 = (const float*)d_in[15]; const float* c3 = (const float*)d_in[16];
    float* out = (float*)d_out;

    int n = in_sizes[1];              // N nodes
    int E = in_sizes[2] / 2;          // edge_index is [2, E]
    if (n > NNODES_MAX) n = NNODES_MAX;
    if (E > EDGES_MAX)  E = EDGES_MAX;

    const int* src32 = ei;
    const int* dst32 = ei + E;

    float *hA, *hB, *xin;
    cudaGetSymbolAddress((void**)&hA,  g_hA);
    cudaGetSymbolAddress((void**)&hB,  g_hB);
    cudaGetSymbolAddress((void**)&xin, g_xin);

    int nb  = (n + 255) / 256;
    int eb  = (E + 255) / 256;
    int nsb = (n + SCAN_BLK - 1) / SCAN_BLK;   // scan blocks (98)

    // --- graph preprocessing (CSR by dst + norms) ---
    zero_kernel<<<nb, 256>>>(n);
    hist_kernel<<<eb, 256>>>(dst32, E);
    dinv_kernel<<<nb, 256>>>(n);
    scan1_kernel<<<nsb, SCAN_BLK>>>(n);
    scan2_kernel<<<1, 128>>>(nsb, n);
    scan3_kernel<<<nsb, SCAN_BLK>>>(n);
    fill_kernel<<<eb, 256>>>(src32, dst32, E);
    concat_kernel<<<(n * 65 + 255) / 256, 256>>>(x, t, n);

    int aggBlocks = (n * 32 + 255) / 256;   // warp per node, 8 warps/block

    // GCN algebra: agg(x @ W) == agg(x) @ W  -> aggregate on the narrower side.
    // L1: GEMM(65->64) then agg_post(64) with b1+gelu
    launch_gemm(xin, W1, nullptr, hA, n, 65, 64, 0);
    agg_kernel<2, true><<<aggBlocks, 256>>>(hA, b1, hB, n);

    // L2: agg_pre(64) then GEMM(64->128) with b2+gelu
    agg_kernel<2, false><<<aggBlocks, 256>>>(hB, nullptr, hA, n);
    launch_gemm(hA, W2, b2, hB, n, 64, 128, 1);

    // L3: agg_pre(128) then GEMM(128->256) with b3+gelu
    agg_kernel<4, false><<<aggBlocks, 256>>>(hB, nullptr, hA, n);
    launch_gemm(hA, W3, b3, hB, n, 128, 256, 1);

    // L4: GEMM(256->128) then agg_post(128) with b4+gelu
    launch_gemm(hB, W4, nullptr, hA, n, 256, 128, 0);
    agg_kernel<4, true><<<aggBlocks, 256>>>(hA, b4, hB, n);

    // --- MLP head ---
    launch_gemm(hB, F1, c1, hA, n, 128, 256, 1);   // bias+gelu
    launch_gemm(hA, F2, c2, hB, n, 256, 128, 1);   // bias+gelu
    launch_gemm(hB, F3, c3, out, n, 128, 64, 2);   // bias only
}

// round 4
// speedup vs baseline: 1.4556x; 1.2468x over previous
#include <cuda_runtime.h>
#include <math.h>
#include <stdint.h>

#define NNODES_MAX 100000
#define EDGES_MAX  3200000
#define SCAN_BLK   1024
#define MAX_SBLOCKS 128

// ---- static scratch ----
__device__ int   g_cnt[NNODES_MAX];
__device__ int   g_cursor[NNODES_MAX];
__device__ int   g_rowptr[NNODES_MAX + 1];
__device__ int   g_bsum[MAX_SBLOCKS];
__device__ float g_dinv[NNODES_MAX];
__device__ int2  g_edges[EDGES_MAX];
__device__ float g_xin[(size_t)NNODES_MAX * 65];
__device__ float g_hA[(size_t)NNODES_MAX * 256];
__device__ float g_hB[(size_t)NNODES_MAX * 256];

__device__ __forceinline__ float gelu_f(float x) {
    float u = 0.7978845608028654f * (x + 0.044715f * x * x * x);
    return 0.5f * x * (1.0f + tanhf(u));
}

__device__ __forceinline__ uint32_t f2tf32(float f) {
    uint32_t u;
    asm("cvt.rna.tf32.f32 %0, %1;" : "=r"(u) : "f"(f));
    return u;
}

__device__ __forceinline__ void mma_tf32(float* c, const uint32_t* a, const uint32_t* b) {
    asm volatile(
        "mma.sync.aligned.m16n8k8.row.col.f32.tf32.tf32.f32 "
        "{%0,%1,%2,%3}, {%4,%5,%6,%7}, {%8,%9}, {%0,%1,%2,%3};"
        : "+f"(c[0]), "+f"(c[1]), "+f"(c[2]), "+f"(c[3])
        : "r"(a[0]), "r"(a[1]), "r"(a[2]), "r"(a[3]), "r"(b[0]), "r"(b[1]));
}

// ---------------- preprocessing ----------------

__global__ void zero_kernel(int n) {
    int i = blockIdx.x * blockDim.x + threadIdx.x;
    if (i < n) { g_cnt[i] = 0; g_cursor[i] = 0; }
}

__global__ void hist_kernel(const int* __restrict__ dst, int E) {
    int i = blockIdx.x * blockDim.x + threadIdx.x;
    if (i < E) atomicAdd(&g_cnt[dst[i]], 1);
}

__global__ void dinv_kernel(int n) {
    int i = blockIdx.x * blockDim.x + threadIdx.x;
    if (i < n) g_dinv[i] = rsqrtf((float)(g_cnt[i] + 1));
}

__global__ void scan1_kernel(int n) {
    __shared__ int ws[32];
    int tid = threadIdx.x, lane = tid & 31, wid = tid >> 5;
    int i = blockIdx.x * SCAN_BLK + tid;
    int v = (i < n) ? g_cnt[i] : 0;
    int x = v;
    #pragma unroll
    for (int off = 1; off < 32; off <<= 1) {
        int t = __shfl_up_sync(0xffffffffu, x, off);
        if (lane >= off) x += t;
    }
    if (lane == 31) ws[wid] = x;
    __syncthreads();
    if (wid == 0) {
        int w = ws[lane];
        #pragma unroll
        for (int off = 1; off < 32; off <<= 1) {
            int t = __shfl_up_sync(0xffffffffu, w, off);
            if (lane >= off) w += t;
        }
        ws[lane] = w;
    }
    __syncthreads();
    int woff = (wid > 0) ? ws[wid - 1] : 0;
    if (i < n) g_rowptr[i] = woff + x - v;
    if (tid == 0) g_bsum[blockIdx.x] = ws[31];
}

__global__ void scan2_kernel(int nb, int n) {
    __shared__ int s[MAX_SBLOCKS];
    int tid = threadIdx.x;
    if (tid < nb) s[tid] = g_bsum[tid];
    __syncthreads();
    if (tid == 0) {
        int run = 0;
        for (int i = 0; i < nb; i++) { int v = s[i]; s[i] = run; run += v; }
        g_rowptr[n] = run;
    }
    __syncthreads();
    if (tid < nb) g_bsum[tid] = s[tid];
}

__global__ void scan3_kernel(int n) {
    int i = blockIdx.x * SCAN_BLK + threadIdx.x;
    if (i < n) g_rowptr[i] += g_bsum[blockIdx.x];
}

__global__ void fill_kernel(const int* __restrict__ src,
                            const int* __restrict__ dst, int E) {
    int i = blockIdx.x * blockDim.x + threadIdx.x;
    if (i < E) {
        int s = src[i];
        int d = dst[i];
        int pos = g_rowptr[d] + atomicAdd(&g_cursor[d], 1);
        g_edges[pos] = make_int2(s, __float_as_int(g_dinv[s] * g_dinv[d]));
    }
}

__global__ void concat_kernel(const float* __restrict__ x, const float* __restrict__ t, int n) {
    int total = n * 65;
    int i = blockIdx.x * blockDim.x + threadIdx.x;
    if (i < total) {
        int row = i / 65;
        int c = i - row * 65;
        g_xin[i] = (c < 64) ? x[(size_t)row * 64 + c] : t[row];
    }
}

// ---------------- TF32 tensor-core GEMM ----------------
// C[M,N] = A[M,K] @ W[K,N]  (+bias/gelu per mode)
// block 128x64, 8 warps as 4(M)x2(N), warp tile 32x32 (2 m16 x 4 n8), KC=16.
// Smem stride 20 floats -> all fragment LDS patterns are bank-conflict-free.
#define AST 20
__global__ void gemm_tc_kernel(const float* __restrict__ A, const float* __restrict__ W,
                               const float* __restrict__ bias, float* __restrict__ C,
                               int M, int K, int N, int mode) {
    __shared__ uint32_t Asm[128 * AST];
    __shared__ uint32_t Wsm[64 * AST];

    int m0 = blockIdx.x * 128;
    int n0 = blockIdx.y * 64;
    int tid = threadIdx.x;
    int wid = tid >> 5;
    int lane = tid & 31;
    int g  = lane >> 2;      // group id (0..7)
    int tg = lane & 3;       // thread-in-group (0..3)
    int wm = (wid & 3) * 32; // warp M offset
    int wn = (wid >> 2) * 32;// warp N offset

    float acc[2][4][4];
    #pragma unroll
    for (int mt = 0; mt < 2; mt++)
        #pragma unroll
        for (int nt = 0; nt < 4; nt++)
            #pragma unroll
            for (int q = 0; q < 4; q++) acc[mt][nt][q] = 0.0f;

    // A load map: row = tid/2, 8 consecutive k's
    int a_row = tid >> 1;
    int a_kg  = (tid & 1) * 8;
    bool a_ok = (m0 + a_row) < M;
    const float* Arow = A + (size_t)(m0 + a_row) * K;
    // W load map: n = tid%64, k = tid/64 + 4j
    int w_n  = tid & 63;
    int w_k0 = tid >> 6;

    int nkc = (K + 15) / 16;
    for (int kci = 0; kci < nkc; kci++) {
        int kc = kci * 16;
        // load A tile (tf32 convert)
        #pragma unroll
        for (int j = 0; j < 8; j++) {
            int gk = kc + a_kg + j;
            float v = (a_ok && gk < K) ? Arow[gk] : 0.0f;
            Asm[a_row * AST + a_kg + j] = f2tf32(v);
        }
        // load W tile transposed: Wsm[n][k]
        #pragma unroll
        for (int j = 0; j < 4; j++) {
            int k = w_k0 + 4 * j;
            int gk = kc + k;
            float v = (gk < K) ? W[(size_t)gk * N + n0 + w_n] : 0.0f;
            Wsm[w_n * AST + k] = f2tf32(v);
        }
        __syncthreads();

        #pragma unroll
        for (int s = 0; s < 2; s++) {
            int kb = s * 8;
            uint32_t afr[2][4], bfr[4][2];
            #pragma unroll
            for (int mt = 0; mt < 2; mt++) {
                int r = wm + mt * 16 + g;
                afr[mt][0] = Asm[r * AST + kb + tg];
                afr[mt][1] = Asm[(r + 8) * AST + kb + tg];
                afr[mt][2] = Asm[r * AST + kb + tg + 4];
                afr[mt][3] = Asm[(r + 8) * AST + kb + tg + 4];
            }
            #pragma unroll
            for (int nt = 0; nt < 4; nt++) {
                int nn = wn + nt * 8 + g;
                bfr[nt][0] = Wsm[nn * AST + kb + tg];
                bfr[nt][1] = Wsm[nn * AST + kb + tg + 4];
            }
            #pragma unroll
            for (int mt = 0; mt < 2; mt++)
                #pragma unroll
                for (int nt = 0; nt < 4; nt++)
                    mma_tf32(acc[mt][nt], afr[mt], bfr[nt]);
        }
        __syncthreads();
    }

    // epilogue
    #pragma unroll
    for (int mt = 0; mt < 2; mt++) {
        int r0 = m0 + wm + mt * 16 + g;
        int r1 = r0 + 8;
        #pragma unroll
        for (int nt = 0; nt < 4; nt++) {
            int cb = n0 + wn + nt * 8 + 2 * tg;
            float bl0 = 0.f, bl1 = 0.f;
            if (mode != 0) { bl0 = bias[cb]; bl1 = bias[cb + 1]; }
            float v0 = acc[mt][nt][0] + bl0;
            float v1 = acc[mt][nt][1] + bl1;
            float v2 = acc[mt][nt][2] + bl0;
            float v3 = acc[mt][nt][3] + bl1;
            if (mode == 1) { v0 = gelu_f(v0); v1 = gelu_f(v1); v2 = gelu_f(v2); v3 = gelu_f(v3); }
            if (r0 < M) { C[(size_t)r0 * N + cb] = v0; C[(size_t)r0 * N + cb + 1] = v1; }
            if (r1 < M) { C[(size_t)r1 * N + cb] = v2; C[(size_t)r1 * N + cb + 1] = v3; }
        }
    }
}

// ---------------- aggregation (warp per node, CSR, no atomics) ----------------
template <int R, bool EPI>   // d = 32*R
__global__ void agg_kernel(const float* __restrict__ h, const float* __restrict__ bias,
                           float* __restrict__ out, int n) {
    int warp = (blockIdx.x * blockDim.x + threadIdx.x) >> 5;
    int lane = threadIdx.x & 31;
    if (warp >= n) return;
    const int d = 32 * R;

    float acc[R];
    #pragma unroll
    for (int r = 0; r < R; r++) acc[r] = 0.0f;

    int beg = g_rowptr[warp];
    int end = g_rowptr[warp + 1];
    for (int base = beg; base < end; base += 32) {
        int2 ed = make_int2(0, 0);
        if (base + lane < end) ed = g_edges[base + lane];
        int cnt = min(32, end - base);
        for (int j = 0; j < cnt; j++) {
            int s   = __shfl_sync(0xffffffffu, ed.x, j);
            float w = __int_as_float(__shfl_sync(0xffffffffu, ed.y, j));
            const float* hr = h + (size_t)s * d + lane;
            #pragma unroll
            for (int r = 0; r < R; r++)
                acc[r] = fmaf(w, __ldg(hr + 32 * r), acc[r]);
        }
    }
    float di = g_dinv[warp];
    float ws = di * di;
    const float* hs = h + (size_t)warp * d + lane;
    #pragma unroll
    for (int r = 0; r < R; r++)
        acc[r] = fmaf(ws, hs[32 * r], acc[r]);

    float* op = out + (size_t)warp * d + lane;
    #pragma unroll
    for (int r = 0; r < R; r++) {
        float v = acc[r];
        if (EPI) v = gelu_f(v + bias[lane + 32 * r]);
        op[32 * r] = v;
    }
}

// ---------------- launch ----------------

static inline void launch_gemm(const float* A, const float* W, const float* bias,
                               float* C, int M, int K, int N, int mode) {
    dim3 grid((M + 127) / 128, N / 64);
    gemm_tc_kernel<<<grid, 256>>>(A, W, bias, C, M, K, N, mode);
}

extern "C" void kernel_launch(void* const* d_in, const int* in_sizes, int n_in,
                              void* d_out, int out_size) {
    const float* x  = (const float*)d_in[0];
    const float* t  = (const float*)d_in[1];
    const int*   ei = (const int*)d_in[2];           // int32
    const float* W1 = (const float*)d_in[3];  const float* b1 = (const float*)d_in[4];
    const float* W2 = (const float*)d_in[5];  const float* b2 = (const float*)d_in[6];
    const float* W3 = (const float*)d_in[7];  const float* b3 = (const float*)d_in[8];
    const float* W4 = (const float*)d_in[9];  const float* b4 = (const float*)d_in[10];
    const float* F1 = (const float*)d_in[11]; const float* c1 = (const float*)d_in[12];
    const float* F2 = (const float*)d_in[13]; const float* c2 = (const float*)d_in[14];
    const float* F3 = (const float*)d_in[15]; const float* c3 = (const float*)d_in[16];
    float* out = (float*)d_out;

    int n = in_sizes[1];
    int E = in_sizes[2] / 2;
    if (n > NNODES_MAX) n = NNODES_MAX;
    if (E > EDGES_MAX)  E = EDGES_MAX;

    const int* src32 = ei;
    const int* dst32 = ei + E;

    float *hA, *hB, *xin;
    cudaGetSymbolAddress((void**)&hA,  g_hA);
    cudaGetSymbolAddress((void**)&hB,  g_hB);
    cudaGetSymbolAddress((void**)&xin, g_xin);

    int nb  = (n + 255) / 256;
    int eb  = (E + 255) / 256;
    int nsb = (n + SCAN_BLK - 1) / SCAN_BLK;

    zero_kernel<<<nb, 256>>>(n);
    hist_kernel<<<eb, 256>>>(dst32, E);
    dinv_kernel<<<nb, 256>>>(n);
    scan1_kernel<<<nsb, SCAN_BLK>>>(n);
    scan2_kernel<<<1, 128>>>(nsb, n);
    scan3_kernel<<<nsb, SCAN_BLK>>>(n);
    fill_kernel<<<eb, 256>>>(src32, dst32, E);
    concat_kernel<<<(n * 65 + 255) / 256, 256>>>(x, t, n);

    int aggBlocks = (n * 32 + 255) / 256;

    // L1: GEMM(65->64) then agg_post(64) with b1+gelu
    launch_gemm(xin, W1, nullptr, hA, n, 65, 64, 0);
    agg_kernel<2, true><<<aggBlocks, 256>>>(hA, b1, hB, n);

    // L2: agg_pre(64) then GEMM(64->128) with b2+gelu
    agg_kernel<2, false><<<aggBlocks, 256>>>(hB, nullptr, hA, n);
    launch_gemm(hA, W2, b2, hB, n, 64, 128, 1);

    // L3: agg_pre(128) then GEMM(128->256) with b3+gelu
    agg_kernel<4, false><<<aggBlocks, 256>>>(hB, nullptr, hA, n);
    launch_gemm(hA, W3, b3, hB, n, 128, 256, 1);

    // L4: GEMM(256->128) then agg_post(128) with b4+gelu
    launch_gemm(hB, W4, nullptr, hA, n, 256, 128, 0);
    agg_kernel<4, true><<<aggBlocks, 256>>>(hA, b4, hB, n);

    // MLP head
    launch_gemm(hB, F1, c1, hA, n, 128, 256, 1);
    launch_gemm(hA, F2, c2, hB, n, 256, 128, 1);
    launch_gemm(hB, F3, c3, out, n, 128, 64, 2);
}

// round 6
// speedup vs baseline: 2.2035x; 1.5138x over previous
#include <cuda_runtime.h>
#include <math.h>
#include <stdint.h>

#define NNODES_MAX 100000
#define EDGES_MAX  3200000
#define SCAN_BLK   1024
#define MAX_SBLOCKS 128
#define XIN_LD     68     // 65 rounded up to 16B-multiple stride (68*4=272B)

// ---- static scratch ----
__device__ int   g_cnt[NNODES_MAX];
__device__ int   g_cursor[NNODES_MAX];
__device__ int   g_rowptr[NNODES_MAX + 1];
__device__ int   g_bsum[MAX_SBLOCKS];
__device__ float g_dinv[NNODES_MAX];
__device__ int2  g_edges[EDGES_MAX];
__device__ __align__(16) float g_xin[(size_t)NNODES_MAX * XIN_LD];
__device__ __align__(16) float g_hA[(size_t)NNODES_MAX * 256];
__device__ __align__(16) float g_hB[(size_t)NNODES_MAX * 256];

__device__ __forceinline__ float gelu_f(float x) {
    float u = 0.7978845608028654f * (x + 0.044715f * x * x * x);
    return 0.5f * x * (1.0f + tanhf(u));
}

__device__ __forceinline__ uint32_t f2tf32(float f) {
    uint32_t u;
    asm("cvt.rna.tf32.f32 %0, %1;" : "=r"(u) : "f"(f));
    return u;
}

__device__ __forceinline__ void mma_tf32(float* c, const uint32_t* a, const uint32_t* b) {
    asm volatile(
        "mma.sync.aligned.m16n8k8.row.col.f32.tf32.tf32.f32 "
        "{%0,%1,%2,%3}, {%4,%5,%6,%7}, {%8,%9}, {%0,%1,%2,%3};"
        : "+f"(c[0]), "+f"(c[1]), "+f"(c[2]), "+f"(c[3])
        : "r"(a[0]), "r"(a[1]), "r"(a[2]), "r"(a[3]), "r"(b[0]), "r"(b[1]));
}

__device__ __forceinline__ void cp_async16(uint32_t sdst, const void* gsrc, int src_bytes) {
    asm volatile("cp.async.cg.shared.global [%0], [%1], 16, %2;"
                 :: "r"(sdst), "l"(gsrc), "r"(src_bytes));
}
__device__ __forceinline__ void cp_commit() {
    asm volatile("cp.async.commit_group;");
}
template <int N>
__device__ __forceinline__ void cp_wait() {
    asm volatile("cp.async.wait_group %0;" :: "n"(N));
}

// ---------------- preprocessing ----------------

__global__ void zero_kernel(int n) {
    int i = blockIdx.x * blockDim.x + threadIdx.x;
    if (i < n) { g_cnt[i] = 0; g_cursor[i] = 0; }
}

__global__ void hist_kernel(const int* __restrict__ dst, int E) {
    int i = blockIdx.x * blockDim.x + threadIdx.x;
    if (i < E) atomicAdd(&g_cnt[dst[i]], 1);
}

__global__ void dinv_kernel(int n) {
    int i = blockIdx.x * blockDim.x + threadIdx.x;
    if (i < n) g_dinv[i] = rsqrtf((float)(g_cnt[i] + 1));
}

__global__ void scan1_kernel(int n) {
    __shared__ int ws[32];
    int tid = threadIdx.x, lane = tid & 31, wid = tid >> 5;
    int i = blockIdx.x * SCAN_BLK + tid;
    int v = (i < n) ? g_cnt[i] : 0;
    int x = v;
    #pragma unroll
    for (int off = 1; off < 32; off <<= 1) {
        int t = __shfl_up_sync(0xffffffffu, x, off);
        if (lane >= off) x += t;
    }
    if (lane == 31) ws[wid] = x;
    __syncthreads();
    if (wid == 0) {
        int w = ws[lane];
        #pragma unroll
        for (int off = 1; off < 32; off <<= 1) {
            int t = __shfl_up_sync(0xffffffffu, w, off);
            if (lane >= off) w += t;
        }
        ws[lane] = w;
    }
    __syncthreads();
    int woff = (wid > 0) ? ws[wid - 1] : 0;
    if (i < n) g_rowptr[i] = woff + x - v;
    if (tid == 0) g_bsum[blockIdx.x] = ws[31];
}

__global__ void scan2_kernel(int nb, int n) {
    __shared__ int s[MAX_SBLOCKS];
    int tid = threadIdx.x;
    if (tid < nb) s[tid] = g_bsum[tid];
    __syncthreads();
    if (tid == 0) {
        int run = 0;
        for (int i = 0; i < nb; i++) { int v = s[i]; s[i] = run; run += v; }
        g_rowptr[n] = run;
    }
    __syncthreads();
    if (tid < nb) g_bsum[tid] = s[tid];
}

__global__ void scan3_kernel(int n) {
    int i = blockIdx.x * SCAN_BLK + threadIdx.x;
    if (i < n) g_rowptr[i] += g_bsum[blockIdx.x];
}

__global__ void fill_kernel(const int* __restrict__ src,
                            const int* __restrict__ dst, int E) {
    int i = blockIdx.x * blockDim.x + threadIdx.x;
    if (i < E) {
        int s = src[i];
        int d = dst[i];
        int pos = g_rowptr[d] + atomicAdd(&g_cursor[d], 1);
        g_edges[pos] = make_int2(s, __float_as_int(g_dinv[s] * g_dinv[d]));
    }
}

__global__ void concat_kernel(const float* __restrict__ x, const float* __restrict__ t, int n) {
    int total = n * 65;
    int i = blockIdx.x * blockDim.x + threadIdx.x;
    if (i < total) {
        int row = i / 65;
        int c = i - row * 65;
        g_xin[(size_t)row * XIN_LD + c] = (c < 64) ? x[(size_t)row * 64 + c] : t[row];
    }
}

// ---------------- TF32 tensor-core GEMM, cp.async double-buffered ----------------
// C[M,N] = A[M,K] @ W[K,N], A row stride = lda (floats, 16B-multiple).
#define AST 20
#define WST 72
__global__ void gemm_tc_kernel(const float* __restrict__ A, const float* __restrict__ W,
                               const float* __restrict__ bias, float* __restrict__ C,
                               int M, int K, int N, int lda, int mode) {
    __shared__ float Asm[2][128 * AST];
    __shared__ float Wsm[2][16 * WST];

    int m0 = blockIdx.x * 128;
    int n0 = blockIdx.y * 64;
    int tid = threadIdx.x;
    int wid = tid >> 5;
    int lane = tid & 31;
    int g  = lane >> 2;
    int tg = lane & 3;
    int wm = (wid & 3) * 32;
    int wn = (wid >> 2) * 32;

    float acc[2][4][4];
    #pragma unroll
    for (int mt = 0; mt < 2; mt++)
        #pragma unroll
        for (int nt = 0; nt < 4; nt++)
            #pragma unroll
            for (int q = 0; q < 4; q++) acc[mt][nt][q] = 0.0f;

    int ar0 = tid >> 2;            // A rows ar0 and ar0+64
    int asg = (tid & 3) * 4;       // 16B segment within 16-wide k chunk
    int wr  = tid >> 4;            // W k-row
    int wsg = (tid & 15) * 4;      // W 16B segment (n direction)

    int nkc = (K + 15) / 16;

    // prefetch tile 0
    {
        #pragma unroll
        for (int j = 0; j < 2; j++) {
            int r = ar0 + 64 * j;
            int gk = asg;
            int bytes = ((m0 + r) < M) ? max(0, min(16, (K - gk) * 4)) : 0;
            const float* src = A + (size_t)min(m0 + r, M - 1) * lda + min(gk, K - 1);
            cp_async16((uint32_t)__cvta_generic_to_shared(&Asm[0][r * AST + asg]), src, bytes);
        }
        {
            int gk = wr;
            int bytes = (gk < K) ? 16 : 0;
            const float* src = W + (size_t)min(gk, K - 1) * N + n0 + wsg;
            cp_async16((uint32_t)__cvta_generic_to_shared(&Wsm[0][wr * WST + wsg]), src, bytes);
        }
        cp_commit();
    }

    int buf = 0;
    for (int kci = 0; kci < nkc; kci++) {
        if (kci + 1 < nkc) {
            int kc = (kci + 1) * 16;
            int nb = buf ^ 1;
            #pragma unroll
            for (int j = 0; j < 2; j++) {
                int r = ar0 + 64 * j;
                int gk = kc + asg;
                int bytes = ((m0 + r) < M) ? max(0, min(16, (K - gk) * 4)) : 0;
                const float* src = A + (size_t)min(m0 + r, M - 1) * lda + min(gk, K - 1);
                cp_async16((uint32_t)__cvta_generic_to_shared(&Asm[nb][r * AST + asg]), src, bytes);
            }
            {
                int gk = kc + wr;
                int bytes = (gk < K) ? 16 : 0;
                const float* src = W + (size_t)min(gk, K - 1) * N + n0 + wsg;
                cp_async16((uint32_t)__cvta_generic_to_shared(&Wsm[nb][wr * WST + wsg]), src, bytes);
            }
        }
        cp_commit();
        cp_wait<1>();
        __syncthreads();

        const float* As = Asm[buf];
        const float* Ws = Wsm[buf];
        #pragma unroll
        for (int s = 0; s < 2; s++) {
            int kb = s * 8;
            uint32_t afr[2][4], bfr[4][2];
            #pragma unroll
            for (int mt = 0; mt < 2; mt++) {
                int r = wm + mt * 16 + g;
                afr[mt][0] = f2tf32(As[r * AST + kb + tg]);
                afr[mt][1] = f2tf32(As[(r + 8) * AST + kb + tg]);
                afr[mt][2] = f2tf32(As[r * AST + kb + tg + 4]);
                afr[mt][3] = f2tf32(As[(r + 8) * AST + kb + tg + 4]);
            }
            #pragma unroll
            for (int nt = 0; nt < 4; nt++) {
                int nn = wn + nt * 8 + g;
                bfr[nt][0] = f2tf32(Ws[(kb + tg) * WST + nn]);
                bfr[nt][1] = f2tf32(Ws[(kb + tg + 4) * WST + nn]);
            }
            #pragma unroll
            for (int mt = 0; mt < 2; mt++)
                #pragma unroll
                for (int nt = 0; nt < 4; nt++)
                    mma_tf32(acc[mt][nt], afr[mt], bfr[nt]);
        }
        __syncthreads();
        buf ^= 1;
    }

    #pragma unroll
    for (int mt = 0; mt < 2; mt++) {
        int r0 = m0 + wm + mt * 16 + g;
        int r1 = r0 + 8;
        #pragma unroll
        for (int nt = 0; nt < 4; nt++) {
            int cb = n0 + wn + nt * 8 + 2 * tg;
            float bl0 = 0.f, bl1 = 0.f;
            if (mode != 0) { bl0 = bias[cb]; bl1 = bias[cb + 1]; }
            float v0 = acc[mt][nt][0] + bl0;
            float v1 = acc[mt][nt][1] + bl1;
            float v2 = acc[mt][nt][2] + bl0;
            float v3 = acc[mt][nt][3] + bl1;
            if (mode == 1) { v0 = gelu_f(v0); v1 = gelu_f(v1); v2 = gelu_f(v2); v3 = gelu_f(v3); }
            if (r0 < M) { C[(size_t)r0 * N + cb] = v0; C[(size_t)r0 * N + cb + 1] = v1; }
            if (r1 < M) { C[(size_t)r1 * N + cb] = v2; C[(size_t)r1 * N + cb + 1] = v3; }
        }
    }
}

// ---------------- aggregation (warp per node, vectorized gathers) ----------------
template <int VW, bool EPI>   // d = 32*VW
__global__ void agg_kernel(const float* __restrict__ h, const float* __restrict__ bias,
                           float* __restrict__ out, int n) {
    int warp = (blockIdx.x * blockDim.x + threadIdx.x) >> 5;
    int lane = threadIdx.x & 31;
    if (warp >= n) return;
    const int d = 32 * VW;
    const int col = lane * VW;

    float acc[VW];
    #pragma unroll
    for (int r = 0; r < VW; r++) acc[r] = 0.0f;

    int beg = g_rowptr[warp];
    int end = g_rowptr[warp + 1];
    for (int base = beg; base < end; base += 32) {
        int2 ed = make_int2(0, 0);
        if (base + lane < end) ed = g_edges[base + lane];
        int cnt = min(32, end - base);
        for (int j = 0; j < cnt; j++) {
            int s   = __shfl_sync(0xffffffffu, ed.x, j);
            float w = __int_as_float(__shfl_sync(0xffffffffu, ed.y, j));
            const float* hr = h + (size_t)s * d + col;
            if (VW == 4) {
                float4 v = __ldg((const float4*)hr);
                acc[0] = fmaf(w, v.x, acc[0]);
                acc[1] = fmaf(w, v.y, acc[1]);
                acc[2] = fmaf(w, v.z, acc[2]);
                acc[3] = fmaf(w, v.w, acc[3]);
            } else {
                float2 v = __ldg((const float2*)hr);
                acc[0] = fmaf(w, v.x, acc[0]);
                acc[1] = fmaf(w, v.y, acc[1]);
            }
        }
    }
    float di = g_dinv[warp];
    float ws = di * di;
    const float* hs = h + (size_t)warp * d + col;
    if (VW == 4) {
        float4 v = *(const float4*)hs;
        acc[0] = fmaf(ws, v.x, acc[0]);
        acc[1] = fmaf(ws, v.y, acc[1]);
        acc[2] = fmaf(ws, v.z, acc[2]);
        acc[3] = fmaf(ws, v.w, acc[3]);
    } else {
        float2 v = *(const float2*)hs;
        acc[0] = fmaf(ws, v.x, acc[0]);
        acc[1] = fmaf(ws, v.y, acc[1]);
    }

    float* op = out + (size_t)warp * d + col;
    if (EPI) {
        #pragma unroll
        for (int r = 0; r < VW; r++) acc[r] = gelu_f(acc[r] + bias[col + r]);
    }
    if (VW == 4) *(float4*)op = make_float4(acc[0], acc[1], acc[2], acc[3]);
    else         *(float2*)op = make_float2(acc[0], acc[1]);
}

// ---------------- launch ----------------

static inline void launch_gemm(const float* A, const float* W, const float* bias,
                               float* C, int M, int K, int N, int lda, int mode) {
    dim3 grid((M + 127) / 128, N / 64);
    gemm_tc_kernel<<<grid, 256>>>(A, W, bias, C, M, K, N, lda, mode);
}

extern "C" void kernel_launch(void* const* d_in, const int* in_sizes, int n_in,
                              void* d_out, int out_size) {
    const float* x  = (const float*)d_in[0];
    const float* t  = (const float*)d_in[1];
    const int*   ei = (const int*)d_in[2];           // int32
    const float* W1 = (const float*)d_in[3];  const float* b1 = (const float*)d_in[4];
    const float* W2 = (const float*)d_in[5];  const float* b2 = (const float*)d_in[6];
    const float* W3 = (const float*)d_in[7];  const float* b3 = (const float*)d_in[8];
    const float* W4 = (const float*)d_in[9];  const float* b4 = (const float*)d_in[10];
    const float* F1 = (const float*)d_in[11]; const float* c1 = (const float*)d_in[12];
    const float* F2 = (const float*)d_in[13]; const float* c2 = (const float*)d_in[14];
    const float* F3 = (const float*)d_in[15]; const float* c3 = (const float*)d_in[16];
    float* out = (float*)d_out;

    int n = in_sizes[1];
    int E = in_sizes[2] / 2;
    if (n > NNODES_MAX) n = NNODES_MAX;
    if (E > EDGES_MAX)  E = EDGES_MAX;

    const int* src32 = ei;
    const int* dst32 = ei + E;

    float *hA, *hB, *xin;
    cudaGetSymbolAddress((void**)&hA,  g_hA);
    cudaGetSymbolAddress((void**)&hB,  g_hB);
    cudaGetSymbolAddress((void**)&xin, g_xin);

    int nb  = (n + 255) / 256;
    int eb  = (E + 255) / 256;
    int nsb = (n + SCAN_BLK - 1) / SCAN_BLK;

    zero_kernel<<<nb, 256>>>(n);
    hist_kernel<<<eb, 256>>>(dst32, E);
    dinv_kernel<<<nb, 256>>>(n);
    scan1_kernel<<<nsb, SCAN_BLK>>>(n);
    scan2_kernel<<<1, 128>>>(nsb, n);
    scan3_kernel<<<nsb, SCAN_BLK>>>(n);
    fill_kernel<<<eb, 256>>>(src32, dst32, E);
    concat_kernel<<<(n * 65 + 255) / 256, 256>>>(x, t, n);

    int aggBlocks = (n * 32 + 255) / 256;

    // L1: GEMM(65->64, lda=68) then agg_post(64) with b1+gelu
    launch_gemm(xin, W1, nullptr, hA, n, 65, 64, XIN_LD, 0);
    agg_kernel<2, true><<<aggBlocks, 256>>>(hA, b1, hB, n);

    // L2: agg_pre(64) then GEMM(64->128) with b2+gelu
    agg_kernel<2, false><<<aggBlocks, 256>>>(hB, nullptr, hA, n);
    launch_gemm(hA, W2, b2, hB, n, 64, 128, 64, 1);

    // L3: agg_pre(128) then GEMM(128->256) with b3+gelu
    agg_kernel<4, false><<<aggBlocks, 256>>>(hB, nullptr, hA, n);
    launch_gemm(hA, W3, b3, hB, n, 128, 256, 128, 1);

    // L4: GEMM(256->128) then agg_post(128) with b4+gelu
    launch_gemm(hB, W4, nullptr, hA, n, 256, 128, 256, 0);
    agg_kernel<4, true><<<aggBlocks, 256>>>(hA, b4, hB, n);

    // MLP head
    launch_gemm(hB, F1, c1, hA, n, 128, 256, 128, 1);
    launch_gemm(hA, F2, c2, hB, n, 256, 128, 256, 1);
    launch_gemm(hB, F3, c3, out, n, 128, 64, 128, 2);
}

// round 8
// speedup vs baseline: 2.2977x; 1.0427x over previous
#include <cuda_runtime.h>
#include <math.h>
#include <stdint.h>

#define NNODES_MAX 100000
#define EDGES_MAX  3200000
#define SCAN_BLK   1024
#define MAX_SBLOCKS 128
#define XIN_LD     68     // 65 padded to 16B-multiple stride

// ---- static scratch ----
__device__ int   g_cnt[NNODES_MAX];
__device__ int   g_rowptr[NNODES_MAX + 1];
__device__ int   g_bsum[MAX_SBLOCKS];
__device__ float g_dinv[NNODES_MAX];
__device__ int2  g_edges[EDGES_MAX];
__device__ __align__(16) float g_xin[(size_t)NNODES_MAX * XIN_LD];
__device__ __align__(16) float g_hA[(size_t)NNODES_MAX * 256];
__device__ __align__(16) float g_hB[(size_t)NNODES_MAX * 256];

__device__ __forceinline__ float gelu_f(float x) {
    float u = 0.7978845608028654f * (x + 0.044715f * x * x * x);
    return 0.5f * x * (1.0f + tanhf(u));
}

__device__ __forceinline__ uint32_t f2tf32(float f) {
    uint32_t u;
    asm("cvt.rna.tf32.f32 %0, %1;" : "=r"(u) : "f"(f));
    return u;
}

__device__ __forceinline__ void mma_tf32(float* c, const uint32_t* a, const uint32_t* b) {
    asm volatile(
        "mma.sync.aligned.m16n8k8.row.col.f32.tf32.tf32.f32 "
        "{%0,%1,%2,%3}, {%4,%5,%6,%7}, {%8,%9}, {%0,%1,%2,%3};"
        : "+f"(c[0]), "+f"(c[1]), "+f"(c[2]), "+f"(c[3])
        : "r"(a[0]), "r"(a[1]), "r"(a[2]), "r"(a[3]), "r"(b[0]), "r"(b[1]));
}

__device__ __forceinline__ void cp_async16(uint32_t sdst, const void* gsrc, int src_bytes) {
    asm volatile("cp.async.cg.shared.global [%0], [%1], 16, %2;"
                 :: "r"(sdst), "l"(gsrc), "r"(src_bytes));
}
__device__ __forceinline__ void cp_commit() {
    asm volatile("cp.async.commit_group;");
}
template <int N>
__device__ __forceinline__ void cp_wait() {
    asm volatile("cp.async.wait_group %0;" :: "n"(N));
}

// ---------------- preprocessing ----------------

__global__ void zero_kernel(int n) {
    int i = blockIdx.x * blockDim.x + threadIdx.x;
    if (i < n) g_cnt[i] = 0;
}

// 4 edges per thread via int4
__global__ void hist_kernel(const int* __restrict__ dst, int E) {
    int i = blockIdx.x * blockDim.x + threadIdx.x;
    int base = i * 4;
    if (base + 3 < E) {
        int4 d = *(const int4*)(dst + base);
        atomicAdd(&g_cnt[d.x], 1);
        atomicAdd(&g_cnt[d.y], 1);
        atomicAdd(&g_cnt[d.z], 1);
        atomicAdd(&g_cnt[d.w], 1);
    } else {
        for (int j = base; j < E; j++) atomicAdd(&g_cnt[dst[j]], 1);
    }
}

// per-block exclusive scan of cnt; also computes dinv (fused)
__global__ void scan1_kernel(int n) {
    __shared__ int ws[32];
    int tid = threadIdx.x, lane = tid & 31, wid = tid >> 5;
    int i = blockIdx.x * SCAN_BLK + tid;
    int v = (i < n) ? g_cnt[i] : 0;
    if (i < n) g_dinv[i] = rsqrtf((float)(v + 1));   // +1 self loop
    int x = v;
    #pragma unroll
    for (int off = 1; off < 32; off <<= 1) {
        int t = __shfl_up_sync(0xffffffffu, x, off);
        if (lane >= off) x += t;
    }
    if (lane == 31) ws[wid] = x;
    __syncthreads();
    if (wid == 0) {
        int w = ws[lane];
        #pragma unroll
        for (int off = 1; off < 32; off <<= 1) {
            int t = __shfl_up_sync(0xffffffffu, w, off);
            if (lane >= off) w += t;
        }
        ws[lane] = w;
    }
    __syncthreads();
    int woff = (wid > 0) ? ws[wid - 1] : 0;
    if (i < n) g_rowptr[i] = woff + x - v;
    if (tid == 0) g_bsum[blockIdx.x] = ws[31];
}

__global__ void scan2_kernel(int nb, int n) {
    __shared__ int s[MAX_SBLOCKS];
    int tid = threadIdx.x;
    if (tid < nb) s[tid] = g_bsum[tid];
    __syncthreads();
    if (tid == 0) {
        int run = 0;
        for (int i = 0; i < nb; i++) { int v = s[i]; s[i] = run; run += v; }
        g_rowptr[n] = run;
    }
    __syncthreads();
    if (tid < nb) g_bsum[tid] = s[tid];
}

__global__ void scan3_kernel(int n) {
    int i = blockIdx.x * SCAN_BLK + threadIdx.x;
    if (i < n) g_rowptr[i] += g_bsum[blockIdx.x];
}

// countdown on g_cnt -> unique slot; g_cnt ends at 0 as side effect
__global__ void fill_kernel(const int* __restrict__ src,
                            const int* __restrict__ dst, int E) {
    int i = blockIdx.x * blockDim.x + threadIdx.x;
    if (i < E) {
        int s = src[i];
        int d = dst[i];
        int pos = g_rowptr[d] + atomicSub(&g_cnt[d], 1) - 1;
        g_edges[pos] = make_int2(s, __float_as_int(g_dinv[s] * g_dinv[d]));
    }
}

// half-warp (16 threads) per row: float4 copies + t
__global__ void concat_kernel(const float* __restrict__ x, const float* __restrict__ t, int n) {
    int gid = blockIdx.x * blockDim.x + threadIdx.x;
    int row = gid >> 4;
    int sub = gid & 15;
    if (row < n) {
        float4 v = *(const float4*)(x + (size_t)row * 64 + sub * 4);
        *(float4*)(g_xin + (size_t)row * XIN_LD + sub * 4) = v;
        if (sub == 0) g_xin[(size_t)row * XIN_LD + 64] = t[row];
    }
}

// ---------------- TF32 tensor-core GEMM, 3-stage cp.async pipeline ----------------
// C[M,N] = A[M,K] @ W[K,N], A row stride lda (floats, 16B-multiple).
#define AST 20
#define WST 72
#define STAGES 3
__global__ void gemm_tc_kernel(const float* __restrict__ A, const float* __restrict__ W,
                               const float* __restrict__ bias, float* __restrict__ C,
                               int M, int K, int N, int lda, int mode) {
    __shared__ float Asm[STAGES][128 * AST];
    __shared__ float Wsm[STAGES][16 * WST];

    int m0 = blockIdx.x * 128;
    int n0 = blockIdx.y * 64;
    int tid = threadIdx.x;
    int wid = tid >> 5;
    int lane = tid & 31;
    int g  = lane >> 2;
    int tg = lane & 3;
    int wm = (wid & 3) * 32;
    int wn = (wid >> 2) * 32;

    float acc[2][4][4];
    #pragma unroll
    for (int mt = 0; mt < 2; mt++)
        #pragma unroll
        for (int nt = 0; nt < 4; nt++)
            #pragma unroll
            for (int q = 0; q < 4; q++) acc[mt][nt][q] = 0.0f;

    int ar0 = tid >> 2;            // A rows ar0 and ar0+64
    int asg = (tid & 3) * 4;       // 16B segment within 16-wide k chunk
    int wr  = tid >> 4;            // W k-row
    int wsg = (tid & 15) * 4;      // W 16B segment

    int nkc = (K + 15) / 16;

    // prefetch tiles 0 .. STAGES-2
    #pragma unroll
    for (int s = 0; s < STAGES - 1; s++) {
        if (s < nkc) {
            int kc = s * 16;
            #pragma unroll
            for (int j = 0; j < 2; j++) {
                int r = ar0 + 64 * j;
                int gk = kc + asg;
                int bytes = ((m0 + r) < M) ? max(0, min(16, (K - gk) * 4)) : 0;
                const float* src = A + (size_t)min(m0 + r, M - 1) * lda + min(gk, K - 1);
                cp_async16((uint32_t)__cvta_generic_to_shared(&Asm[s][r * AST + asg]), src, bytes);
            }
            int gk = kc + wr;
            int bytes = (gk < K) ? 16 : 0;
            const float* wsrc = W + (size_t)min(gk, K - 1) * N + n0 + wsg;
            cp_async16((uint32_t)__cvta_generic_to_shared(&Wsm[s][wr * WST + wsg]), wsrc, bytes);
        }
        cp_commit();
    }

    for (int kci = 0; kci < nkc; kci++) {
        cp_wait<STAGES - 2>();     // tile kci complete
        __syncthreads();           // all warps done with the buffer being refilled below

        // prefetch tile kci+STAGES-1 into its (now free) buffer
        {
            int pf = kci + STAGES - 1;
            if (pf < nkc) {
                int pb = pf % STAGES;
                int kc = pf * 16;
                #pragma unroll
                for (int j = 0; j < 2; j++) {
                    int r = ar0 + 64 * j;
                    int gk = kc + asg;
                    int bytes = ((m0 + r) < M) ? max(0, min(16, (K - gk) * 4)) : 0;
                    const float* src = A + (size_t)min(m0 + r, M - 1) * lda + min(gk, K - 1);
                    cp_async16((uint32_t)__cvta_generic_to_shared(&Asm[pb][r * AST + asg]), src, bytes);
                }
                int gk = kc + wr;
                int bytes = (gk < K) ? 16 : 0;
                const float* wsrc = W + (size_t)min(gk, K - 1) * N + n0 + wsg;
                cp_async16((uint32_t)__cvta_generic_to_shared(&Wsm[pb][wr * WST + wsg]), wsrc, bytes);
            }
            cp_commit();
        }

        const float* As = Asm[kci % STAGES];
        const float* Ws = Wsm[kci % STAGES];
        #pragma unroll
        for (int s = 0; s < 2; s++) {
            int kb = s * 8;
            uint32_t afr[2][4], bfr[4][2];
            #pragma unroll
            for (int mt = 0; mt < 2; mt++) {
                int r = wm + mt * 16 + g;
                afr[mt][0] = f2tf32(As[r * AST + kb + tg]);
                afr[mt][1] = f2tf32(As[(r + 8) * AST + kb + tg]);
                afr[mt][2] = f2tf32(As[r * AST + kb + tg + 4]);
                afr[mt][3] = f2tf32(As[(r + 8) * AST + kb + tg + 4]);
            }
            #pragma unroll
            for (int nt = 0; nt < 4; nt++) {
                int nn = wn + nt * 8 + g;
                bfr[nt][0] = f2tf32(Ws[(kb + tg) * WST + nn]);
                bfr[nt][1] = f2tf32(Ws[(kb + tg + 4) * WST + nn]);
            }
            #pragma unroll
            for (int mt = 0; mt < 2; mt++)
                #pragma unroll
                for (int nt = 0; nt < 4; nt++)
                    mma_tf32(acc[mt][nt], afr[mt], bfr[nt]);
        }
    }

    #pragma unroll
    for (int mt = 0; mt < 2; mt++) {
        int r0 = m0 + wm + mt * 16 + g;
        int r1 = r0 + 8;
        #pragma unroll
        for (int nt = 0; nt < 4; nt++) {
            int cb = n0 + wn + nt * 8 + 2 * tg;
            float bl0 = 0.f, bl1 = 0.f;
            if (mode != 0) { bl0 = bias[cb]; bl1 = bias[cb + 1]; }
            float v0 = acc[mt][nt][0] + bl0;
            float v1 = acc[mt][nt][1] + bl1;
            float v2 = acc[mt][nt][2] + bl0;
            float v3 = acc[mt][nt][3] + bl1;
            if (mode == 1) { v0 = gelu_f(v0); v1 = gelu_f(v1); v2 = gelu_f(v2); v3 = gelu_f(v3); }
            if (r0 < M) { C[(size_t)r0 * N + cb] = v0; C[(size_t)r0 * N + cb + 1] = v1; }
            if (r1 < M) { C[(size_t)r1 * N + cb] = v2; C[(size_t)r1 * N + cb + 1] = v3; }
        }
    }
}

// ---------------- aggregation (warp per node, vectorized gathers) ----------------
template <int VW, bool EPI>   // d = 32*VW
__global__ void agg_kernel(const float* __restrict__ h, const float* __restrict__ bias,
                           float* __restrict__ out, int n) {
    int warp = (blockIdx.x * blockDim.x + threadIdx.x) >> 5;
    int lane = threadIdx.x & 31;
    if (warp >= n) return;
    const int d = 32 * VW;
    const int col = lane * VW;

    float acc[VW];
    #pragma unroll
    for (int r = 0; r < VW; r++) acc[r] = 0.0f;

    int beg = g_rowptr[warp];
    int end = g_rowptr[warp + 1];
    for (int base = beg; base < end; base += 32) {
        int2 ed = make_int2(0, 0);
        if (base + lane < end) ed = g_edges[base + lane];
        int cnt = min(32, end - base);
        for (int j = 0; j < cnt; j++) {
            int s   = __shfl_sync(0xffffffffu, ed.x, j);
            float w = __int_as_float(__shfl_sync(0xffffffffu, ed.y, j));
            const float* hr = h + (size_t)s * d + col;
            if (VW == 4) {
                float4 v = *(const float4*)hr;
                acc[0] = fmaf(w, v.x, acc[0]);
                acc[1] = fmaf(w, v.y, acc[1]);
                acc[2] = fmaf(w, v.z, acc[2]);
                acc[3] = fmaf(w, v.w, acc[3]);
            } else {
                float2 v = *(const float2*)hr;
                acc[0] = fmaf(w, v.x, acc[0]);
                acc[1] = fmaf(w, v.y, acc[1]);
            }
        }
    }
    float di = g_dinv[warp];
    float ws = di * di;
    const float* hs = h + (size_t)warp * d + col;
    if (VW == 4) {
        float4 v = *(const float4*)hs;
        acc[0] = fmaf(ws, v.x, acc[0]);
        acc[1] = fmaf(ws, v.y, acc[1]);
        acc[2] = fmaf(ws, v.z, acc[2]);
        acc[3] = fmaf(ws, v.w, acc[3]);
    } else {
        float2 v = *(const float2*)hs;
        acc[0] = fmaf(ws, v.x, acc[0]);
        acc[1] = fmaf(ws, v.y, acc[1]);
    }

    float* op = out + (size_t)warp * d + col;
    if (EPI) {
        #pragma unroll
        for (int r = 0; r < VW; r++) acc[r] = gelu_f(acc[r] + bias[col + r]);
    }
    if (VW == 4) *(float4*)op = make_float4(acc[0], acc[1], acc[2], acc[3]);
    else         *(float2*)op = make_float2(acc[0], acc[1]);
}

// ---------------- launch ----------------

static inline void launch_gemm(const float* A, const float* W, const float* bias,
                               float* C, int M, int K, int N, int lda, int mode) {
    dim3 grid((M + 127) / 128, N / 64);
    gemm_tc_kernel<<<grid, 256>>>(A, W, bias, C, M, K, N, lda, mode);
}

extern "C" void kernel_launch(void* const* d_in, const int* in_sizes, int n_in,
                              void* d_out, int out_size) {
    const float* x  = (const float*)d_in[0];
    const float* t  = (const float*)d_in[1];
    const int*   ei = (const int*)d_in[2];           // int32
    const float* W1 = (const float*)d_in[3];  const float* b1 = (const float*)d_in[4];
    const float* W2 = (const float*)d_in[5];  const float* b2 = (const float*)d_in[6];
    const float* W3 = (const float*)d_in[7];  const float* b3 = (const float*)d_in[8];
    const float* W4 = (const float*)d_in[9];  const float* b4 = (const float*)d_in[10];
    const float* F1 = (const float*)d_in[11]; const float* c1 = (const float*)d_in[12];
    const float* F2 = (const float*)d_in[13]; const float* c2 = (const float*)d_in[14];
    const float* F3 = (const float*)d_in[15]; const float* c3 = (const float*)d_in[16];
    float* out = (float*)d_out;

    int n = in_sizes[1];
    int E = in_sizes[2] / 2;
    if (n > NNODES_MAX) n = NNODES_MAX;
    if (E > EDGES_MAX)  E = EDGES_MAX;

    const int* src32 = ei;
    const int* dst32 = ei + E;

    float *hA, *hB, *xin;
    cudaGetSymbolAddress((void**)&hA,  g_hA);
    cudaGetSymbolAddress((void**)&hB,  g_hB);
    cudaGetSymbolAddress((void**)&xin, g_xin);

    int nb  = (n + 255) / 256;
    int eb4 = (E / 4 + 256) / 256;
    int eb  = (E + 255) / 256;
    int nsb = (n + SCAN_BLK - 1) / SCAN_BLK;

    zero_kernel<<<nb, 256>>>(n);
    hist_kernel<<<eb4, 256>>>(dst32, E);
    scan1_kernel<<<nsb, SCAN_BLK>>>(n);       // also computes dinv
    scan2_kernel<<<1, 128>>>(nsb, n);
    scan3_kernel<<<nsb, SCAN_BLK>>>(n);
    fill_kernel<<<eb, 256>>>(src32, dst32, E);
    concat_kernel<<<(n * 16 + 255) / 256, 256>>>(x, t, n);

    int aggBlocks = (n * 32 + 255) / 256;

    // L1: GEMM(65->64, lda=68) then agg_post(64) with b1+gelu
    launch_gemm(xin, W1, nullptr, hA, n, 65, 64, XIN_LD, 0);
    agg_kernel<2, true><<<aggBlocks, 256>>>(hA, b1, hB, n);

    // L2: agg_pre(64) then GEMM(64->128) with b2+gelu
    agg_kernel<2, false><<<aggBlocks, 256>>>(hB, nullptr, hA, n);
    launch_gemm(hA, W2, b2, hB, n, 64, 128, 64, 1);

    // L3: agg_pre(128) then GEMM(128->256) with b3+gelu
    agg_kernel<4, false><<<aggBlocks, 256>>>(hB, nullptr, hA, n);
    launch_gemm(hA, W3, b3, hB, n, 128, 256, 128, 1);

    // L4: GEMM(256->128) then agg_post(128) with b4+gelu
    launch_gemm(hB, W4, nullptr, hA, n, 256, 128, 256, 0);
    agg_kernel<4, true><<<aggBlocks, 256>>>(hA, b4, hB, n);

    // MLP head
    launch_gemm(hB, F1, c1, hA, n, 128, 256, 128, 1);
    launch_gemm(hA, F2, c2, hB, n, 256, 128, 256, 1);
    launch_gemm(hB, F3, c3, out, n, 128, 64, 128, 2);
}

// round 9
// speedup vs baseline: 2.4111x; 1.0494x over previous
#include <cuda_runtime.h>
#include <math.h>
#include <stdint.h>

#define NNODES_MAX 100000
#define EDGES_MAX  3200000
#define SCAN_BLK   1024
#define MAX_SBLOCKS 128
#define XIN_LD     68     // 65 padded to 16B-multiple stride
#define WRND_MAX   160000

// ---- static scratch ----
__device__ int   g_cnt[NNODES_MAX];
__device__ int   g_rowptr[NNODES_MAX + 1];
__device__ int   g_bsum[MAX_SBLOCKS];
__device__ float g_dinv[NNODES_MAX];
__device__ int2  g_edges[EDGES_MAX];
__device__ __align__(16) float g_xin[(size_t)NNODES_MAX * XIN_LD];
__device__ __align__(16) float g_hA[(size_t)NNODES_MAX * 256];
__device__ __align__(16) float g_hB[(size_t)NNODES_MAX * 256];
__device__ __align__(16) float g_wrnd[WRND_MAX];   // tf32-rounded weights

__device__ __forceinline__ float gelu_f(float x) {
    float u = 0.7978845608028654f * (x + 0.044715f * x * x * x);
    return 0.5f * x * (1.0f + tanhf(u));
}

__device__ __forceinline__ float tf32r(float f) {
    uint32_t u;
    asm("cvt.rna.tf32.f32 %0, %1;" : "=r"(u) : "f"(f));
    return __uint_as_float(u);
}

__device__ __forceinline__ void mma_tf32(float* c, const uint32_t* a, const uint32_t* b) {
    asm volatile(
        "mma.sync.aligned.m16n8k8.row.col.f32.tf32.tf32.f32 "
        "{%0,%1,%2,%3}, {%4,%5,%6,%7}, {%8,%9}, {%0,%1,%2,%3};"
        : "+f"(c[0]), "+f"(c[1]), "+f"(c[2]), "+f"(c[3])
        : "r"(a[0]), "r"(a[1]), "r"(a[2]), "r"(a[3]), "r"(b[0]), "r"(b[1]));
}

__device__ __forceinline__ void cp_async16(uint32_t sdst, const void* gsrc, int src_bytes) {
    asm volatile("cp.async.cg.shared.global [%0], [%1], 16, %2;"
                 :: "r"(sdst), "l"(gsrc), "r"(src_bytes));
}
__device__ __forceinline__ void cp_commit() {
    asm volatile("cp.async.commit_group;");
}
template <int N>
__device__ __forceinline__ void cp_wait() {
    asm volatile("cp.async.wait_group %0;" :: "n"(N));
}

// ---------------- preprocessing ----------------

__global__ void zero_kernel(int n) {
    int i = blockIdx.x * blockDim.x + threadIdx.x;
    if (i < n) g_cnt[i] = 0;
}

__global__ void hist_kernel(const int* __restrict__ dst, int E) {
    int i = blockIdx.x * blockDim.x + threadIdx.x;
    int base = i * 4;
    if (base + 3 < E) {
        int4 d = *(const int4*)(dst + base);
        atomicAdd(&g_cnt[d.x], 1);
        atomicAdd(&g_cnt[d.y], 1);
        atomicAdd(&g_cnt[d.z], 1);
        atomicAdd(&g_cnt[d.w], 1);
    } else {
        for (int j = base; j < E; j++) atomicAdd(&g_cnt[dst[j]], 1);
    }
}

__global__ void scan1_kernel(int n) {
    __shared__ int ws[32];
    int tid = threadIdx.x, lane = tid & 31, wid = tid >> 5;
    int i = blockIdx.x * SCAN_BLK + tid;
    int v = (i < n) ? g_cnt[i] : 0;
    if (i < n) g_dinv[i] = rsqrtf((float)(v + 1));
    int x = v;
    #pragma unroll
    for (int off = 1; off < 32; off <<= 1) {
        int t = __shfl_up_sync(0xffffffffu, x, off);
        if (lane >= off) x += t;
    }
    if (lane == 31) ws[wid] = x;
    __syncthreads();
    if (wid == 0) {
        int w = ws[lane];
        #pragma unroll
        for (int off = 1; off < 32; off <<= 1) {
            int t = __shfl_up_sync(0xffffffffu, w, off);
            if (lane >= off) w += t;
        }
        ws[lane] = w;
    }
    __syncthreads();
    int woff = (wid > 0) ? ws[wid - 1] : 0;
    if (i < n) g_rowptr[i] = woff + x - v;
    if (tid == 0) g_bsum[blockIdx.x] = ws[31];
}

__global__ void scan2_kernel(int nb, int n) {
    __shared__ int s[MAX_SBLOCKS];
    int tid = threadIdx.x;
    if (tid < nb) s[tid] = g_bsum[tid];
    __syncthreads();
    if (tid == 0) {
        int run = 0;
        for (int i = 0; i < nb; i++) { int v = s[i]; s[i] = run; run += v; }
        g_rowptr[n] = run;
    }
    __syncthreads();
    if (tid < nb) g_bsum[tid] = s[tid];
}

__global__ void scan3_kernel(int n) {
    int i = blockIdx.x * SCAN_BLK + threadIdx.x;
    if (i < n) g_rowptr[i] += g_bsum[blockIdx.x];
}

__global__ void fill_kernel(const int* __restrict__ src,
                            const int* __restrict__ dst, int E) {
    int i = blockIdx.x * blockDim.x + threadIdx.x;
    if (i < E) {
        int s = src[i];
        int d = dst[i];
        int pos = g_rowptr[d] + atomicSub(&g_cnt[d], 1) - 1;
        g_edges[pos] = make_int2(s, __float_as_int(g_dinv[s] * g_dinv[d]));
    }
}

// concat + tf32 round (xin feeds GEMM1 only)
__global__ void concat_kernel(const float* __restrict__ x, const float* __restrict__ t, int n) {
    int gid = blockIdx.x * blockDim.x + threadIdx.x;
    int row = gid >> 4;
    int sub = gid & 15;
    if (row < n) {
        float4 v = *(const float4*)(x + (size_t)row * 64 + sub * 4);
        v.x = tf32r(v.x); v.y = tf32r(v.y); v.z = tf32r(v.z); v.w = tf32r(v.w);
        *(float4*)(g_xin + (size_t)row * XIN_LD + sub * 4) = v;
        if (sub == 0) g_xin[(size_t)row * XIN_LD + 64] = tf32r(t[row]);
    }
}

// round a weight matrix into g_wrnd + off
__global__ void roundw_kernel(const float* __restrict__ w, int off, int count) {
    int i = blockIdx.x * blockDim.x + threadIdx.x;
    if (i < count) g_wrnd[off + i] = tf32r(w[i]);
}

// ---------------- TF32 tensor-core GEMM, 3-stage cp.async pipeline ----------------
// Inputs (A and W) are pre-rounded to tf32 -> inner loop is pure LDS+MMA.
// mode bits: 1=bias, 2=gelu, 4=round output to tf32
#define MBIAS 1
#define MGELU 2
#define MRND  4
#define AST 20
#define WST 72
#define STAGES 3
__global__ void gemm_tc_kernel(const float* __restrict__ A, const float* __restrict__ W,
                               const float* __restrict__ bias, float* __restrict__ C,
                               int M, int K, int N, int lda, int mode) {
    __shared__ float Asm[STAGES][128 * AST];
    __shared__ float Wsm[STAGES][16 * WST];

    int m0 = blockIdx.x * 128;
    int n0 = blockIdx.y * 64;
    int tid = threadIdx.x;
    int wid = tid >> 5;
    int lane = tid & 31;
    int g  = lane >> 2;
    int tg = lane & 3;
    int wm = (wid & 3) * 32;
    int wn = (wid >> 2) * 32;

    float acc[2][4][4];
    #pragma unroll
    for (int mt = 0; mt < 2; mt++)
        #pragma unroll
        for (int nt = 0; nt < 4; nt++)
            #pragma unroll
            for (int q = 0; q < 4; q++) acc[mt][nt][q] = 0.0f;

    int ar0 = tid >> 2;
    int asg = (tid & 3) * 4;
    int wr  = tid >> 4;
    int wsg = (tid & 15) * 4;

    int nkc = (K + 15) / 16;

    #pragma unroll
    for (int s = 0; s < STAGES - 1; s++) {
        if (s < nkc) {
            int kc = s * 16;
            #pragma unroll
            for (int j = 0; j < 2; j++) {
                int r = ar0 + 64 * j;
                int gk = kc + asg;
                int bytes = ((m0 + r) < M) ? max(0, min(16, (K - gk) * 4)) : 0;
                const float* src = A + (size_t)min(m0 + r, M - 1) * lda + min(gk, K - 1);
                cp_async16((uint32_t)__cvta_generic_to_shared(&Asm[s][r * AST + asg]), src, bytes);
            }
            int gk = kc + wr;
            int bytes = (gk < K) ? 16 : 0;
            const float* wsrc = W + (size_t)min(gk, K - 1) * N + n0 + wsg;
            cp_async16((uint32_t)__cvta_generic_to_shared(&Wsm[s][wr * WST + wsg]), wsrc, bytes);
        }
        cp_commit();
    }

    for (int kci = 0; kci < nkc; kci++) {
        cp_wait<STAGES - 2>();
        __syncthreads();

        {
            int pf = kci + STAGES - 1;
            if (pf < nkc) {
                int pb = pf % STAGES;
                int kc = pf * 16;
                #pragma unroll
                for (int j = 0; j < 2; j++) {
                    int r = ar0 + 64 * j;
                    int gk = kc + asg;
                    int bytes = ((m0 + r) < M) ? max(0, min(16, (K - gk) * 4)) : 0;
                    const float* src = A + (size_t)min(m0 + r, M - 1) * lda + min(gk, K - 1);
                    cp_async16((uint32_t)__cvta_generic_to_shared(&Asm[pb][r * AST + asg]), src, bytes);
                }
                int gk = kc + wr;
                int bytes = (gk < K) ? 16 : 0;
                const float* wsrc = W + (size_t)min(gk, K - 1) * N + n0 + wsg;
                cp_async16((uint32_t)__cvta_generic_to_shared(&Wsm[pb][wr * WST + wsg]), wsrc, bytes);
            }
            cp_commit();
        }

        const float* As = Asm[kci % STAGES];
        const float* Ws = Wsm[kci % STAGES];
        #pragma unroll
        for (int s = 0; s < 2; s++) {
            int kb = s * 8;
            uint32_t afr[2][4], bfr[4][2];
            #pragma unroll
            for (int mt = 0; mt < 2; mt++) {
                int r = wm + mt * 16 + g;
                afr[mt][0] = __float_as_uint(As[r * AST + kb + tg]);
                afr[mt][1] = __float_as_uint(As[(r + 8) * AST + kb + tg]);
                afr[mt][2] = __float_as_uint(As[r * AST + kb + tg + 4]);
                afr[mt][3] = __float_as_uint(As[(r + 8) * AST + kb + tg + 4]);
            }
            #pragma unroll
            for (int nt = 0; nt < 4; nt++) {
                int nn = wn + nt * 8 + g;
                bfr[nt][0] = __float_as_uint(Ws[(kb + tg) * WST + nn]);
                bfr[nt][1] = __float_as_uint(Ws[(kb + tg + 4) * WST + nn]);
            }
            #pragma unroll
            for (int mt = 0; mt < 2; mt++)
                #pragma unroll
                for (int nt = 0; nt < 4; nt++)
                    mma_tf32(acc[mt][nt], afr[mt], bfr[nt]);
        }
    }

    #pragma unroll
    for (int mt = 0; mt < 2; mt++) {
        int r0 = m0 + wm + mt * 16 + g;
        int r1 = r0 + 8;
        #pragma unroll
        for (int nt = 0; nt < 4; nt++) {
            int cb = n0 + wn + nt * 8 + 2 * tg;
            float bl0 = 0.f, bl1 = 0.f;
            if (mode & MBIAS) { bl0 = bias[cb]; bl1 = bias[cb + 1]; }
            float v0 = acc[mt][nt][0] + bl0;
            float v1 = acc[mt][nt][1] + bl1;
            float v2 = acc[mt][nt][2] + bl0;
            float v3 = acc[mt][nt][3] + bl1;
            if (mode & MGELU) { v0 = gelu_f(v0); v1 = gelu_f(v1); v2 = gelu_f(v2); v3 = gelu_f(v3); }
            if (mode & MRND)  { v0 = tf32r(v0); v1 = tf32r(v1); v2 = tf32r(v2); v3 = tf32r(v3); }
            if (r0 < M) { C[(size_t)r0 * N + cb] = v0; C[(size_t)r0 * N + cb + 1] = v1; }
            if (r1 < M) { C[(size_t)r1 * N + cb] = v2; C[(size_t)r1 * N + cb + 1] = v3; }
        }
    }
}

// ---------------- aggregation (warp per node, vectorized gathers) ----------------
// RND: round outputs to tf32 (when they feed a GEMM)
template <int VW, bool EPI, bool RND>
__global__ void agg_kernel(const float* __restrict__ h, const float* __restrict__ bias,
                           float* __restrict__ out, int n) {
    int warp = (blockIdx.x * blockDim.x + threadIdx.x) >> 5;
    int lane = threadIdx.x & 31;
    if (warp >= n) return;
    const int d = 32 * VW;
    const int col = lane * VW;

    float acc[VW];
    #pragma unroll
    for (int r = 0; r < VW; r++) acc[r] = 0.0f;

    int beg = g_rowptr[warp];
    int end = g_rowptr[warp + 1];
    for (int base = beg; base < end; base += 32) {
        int2 ed = make_int2(0, 0);
        if (base + lane < end) ed = g_edges[base + lane];
        int cnt = min(32, end - base);
        for (int j = 0; j < cnt; j++) {
            int s   = __shfl_sync(0xffffffffu, ed.x, j);
            float w = __int_as_float(__shfl_sync(0xffffffffu, ed.y, j));
            const float* hr = h + (size_t)s * d + col;
            if (VW == 4) {
                float4 v = *(const float4*)hr;
                acc[0] = fmaf(w, v.x, acc[0]);
                acc[1] = fmaf(w, v.y, acc[1]);
                acc[2] = fmaf(w, v.z, acc[2]);
                acc[3] = fmaf(w, v.w, acc[3]);
            } else {
                float2 v = *(const float2*)hr;
                acc[0] = fmaf(w, v.x, acc[0]);
                acc[1] = fmaf(w, v.y, acc[1]);
            }
        }
    }
    float di = g_dinv[warp];
    float ws = di * di;
    const float* hs = h + (size_t)warp * d + col;
    if (VW == 4) {
        float4 v = *(const float4*)hs;
        acc[0] = fmaf(ws, v.x, acc[0]);
        acc[1] = fmaf(ws, v.y, acc[1]);
        acc[2] = fmaf(ws, v.z, acc[2]);
        acc[3] = fmaf(ws, v.w, acc[3]);
    } else {
        float2 v = *(const float2*)hs;
        acc[0] = fmaf(ws, v.x, acc[0]);
        acc[1] = fmaf(ws, v.y, acc[1]);
    }

    float* op = out + (size_t)warp * d + col;
    #pragma unroll
    for (int r = 0; r < VW; r++) {
        float v = acc[r];
        if (EPI) v = gelu_f(v + bias[col + r]);
        if (RND) v = tf32r(v);
        acc[r] = v;
    }
    if (VW == 4) *(float4*)op = make_float4(acc[0], acc[1], acc[2], acc[3]);
    else         *(float2*)op = make_float2(acc[0], acc[1]);
}

// ---------------- launch ----------------

static inline void launch_gemm(cudaStream_t st, const float* A, const float* W,
                               const float* bias, float* C,
                               int M, int K, int N, int lda, int mode) {
    dim3 grid((M + 127) / 128, N / 64);
    gemm_tc_kernel<<<grid, 256, 0, st>>>(A, W, bias, C, M, K, N, lda, mode);
}

extern "C" void kernel_launch(void* const* d_in, const int* in_sizes, int n_in,
                              void* d_out, int out_size) {
    const float* x  = (const float*)d_in[0];
    const float* t  = (const float*)d_in[1];
    const int*   ei = (const int*)d_in[2];           // int32
    const float* W1 = (const float*)d_in[3];  const float* b1 = (const float*)d_in[4];
    const float* W2 = (const float*)d_in[5];  const float* b2 = (const float*)d_in[6];
    const float* W3 = (const float*)d_in[7];  const float* b3 = (const float*)d_in[8];
    const float* W4 = (const float*)d_in[9];  const float* b4 = (const float*)d_in[10];
    const float* F1 = (const float*)d_in[11]; const float* c1 = (const float*)d_in[12];
    const float* F2 = (const float*)d_in[13]; const float* c2 = (const float*)d_in[14];
    const float* F3 = (const float*)d_in[15]; const float* c3 = (const float*)d_in[16];
    float* out = (float*)d_out;

    int n = in_sizes[1];
    int E = in_sizes[2] / 2;
    if (n > NNODES_MAX) n = NNODES_MAX;
    if (E > EDGES_MAX)  E = EDGES_MAX;

    const int* src32 = ei;
    const int* dst32 = ei + E;

    float *hA, *hB, *xin, *wr;
    cudaGetSymbolAddress((void**)&hA,  g_hA);
    cudaGetSymbolAddress((void**)&hB,  g_hB);
    cudaGetSymbolAddress((void**)&xin, g_xin);
    cudaGetSymbolAddress((void**)&wr,  g_wrnd);

    // lazy one-time stream/event creation (first call is the uncaptured
    // correctness run; same launches are issued on every call)
    static cudaStream_t s2 = nullptr;
    static cudaEvent_t evFork = nullptr, evJoin = nullptr;
    if (s2 == nullptr) {
        cudaStreamCreateWithFlags(&s2, cudaStreamNonBlocking);
        cudaEventCreateWithFlags(&evFork, cudaEventDisableTiming);
        cudaEventCreateWithFlags(&evJoin, cudaEventDisableTiming);
    }
    cudaStream_t s0 = 0;   // harness capture stream (legacy default)

    int nb  = (n + 255) / 256;
    int eb4 = (E / 4 + 256) / 256;
    int eb  = (E + 255) / 256;
    int nsb = (n + SCAN_BLK - 1) / SCAN_BLK;

    // fork: CSR preprocessing on s2, concat+roundW+GEMM1 on s0
    cudaEventRecord(evFork, s0);
    cudaStreamWaitEvent(s2, evFork, 0);

    zero_kernel<<<nb, 256, 0, s2>>>(n);
    hist_kernel<<<eb4, 256, 0, s2>>>(dst32, E);
    scan1_kernel<<<nsb, SCAN_BLK, 0, s2>>>(n);
    scan2_kernel<<<1, 128, 0, s2>>>(nsb, n);
    scan3_kernel<<<nsb, SCAN_BLK, 0, s2>>>(n);
    fill_kernel<<<eb, 256, 0, s2>>>(src32, dst32, E);
    cudaEventRecord(evJoin, s2);

    // weight rounding offsets in g_wrnd
    const int oW1 = 0,      nW1 = 65 * 64;
    const int oW2 = 4160,   nW2 = 64 * 128;
    const int oW3 = 12352,  nW3 = 128 * 256;
    const int oW4 = 45120,  nW4 = 256 * 128;
    const int oF1 = 77888,  nF1 = 128 * 256;
    const int oF2 = 110656, nF2 = 256 * 128;
    const int oF3 = 143424, nF3 = 128 * 64;
    roundw_kernel<<<(nW1 + 255) / 256, 256, 0, s0>>>(W1, oW1, nW1);
    roundw_kernel<<<(nW2 + 255) / 256, 256, 0, s0>>>(W2, oW2, nW2);
    roundw_kernel<<<(nW3 + 255) / 256, 256, 0, s0>>>(W3, oW3, nW3);
    roundw_kernel<<<(nW4 + 255) / 256, 256, 0, s0>>>(W4, oW4, nW4);
    roundw_kernel<<<(nF1 + 255) / 256, 256, 0, s0>>>(F1, oF1, nF1);
    roundw_kernel<<<(nF2 + 255) / 256, 256, 0, s0>>>(F2, oF2, nF2);
    roundw_kernel<<<(nF3 + 255) / 256, 256, 0, s0>>>(F3, oF3, nF3);
    concat_kernel<<<(n * 16 + 255) / 256, 256, 0, s0>>>(x, t, n);

    int aggBlocks = (n * 32 + 255) / 256;

    // L1 GEMM (independent of CSR)
    launch_gemm(s0, xin, wr + oW1, nullptr, hA, n, 65, 64, XIN_LD, 0);

    // join: CSR ready before first aggregation
    cudaStreamWaitEvent(s0, evJoin, 0);

    // L1 agg_post(64): gelu(b1+..), feeds agg_pre L2 -> no round
    agg_kernel<2, true, false><<<aggBlocks, 256, 0, s0>>>(hA, b1, hB, n);

    // L2: agg_pre(64) [round: feeds GEMM2] then GEMM2 b2+gelu [feeds agg -> no round]
    agg_kernel<2, false, true><<<aggBlocks, 256, 0, s0>>>(hB, nullptr, hA, n);
    launch_gemm(s0, hA, wr + oW2, b2, hB, n, 64, 128, 64, MBIAS | MGELU);

    // L3: agg_pre(128) [round] then GEMM3 b3+gelu [feeds GEMM4 -> round]
    agg_kernel<4, false, true><<<aggBlocks, 256, 0, s0>>>(hB, nullptr, hA, n);
    launch_gemm(s0, hA, wr + oW3, b3, hB, n, 128, 256, 128, MBIAS | MGELU | MRND);

    // L4: GEMM4 [feeds agg -> no round] then agg_post(128) b4+gelu [feeds F1 -> round]
    launch_gemm(s0, hB, wr + oW4, nullptr, hA, n, 256, 128, 256, 0);
    agg_kernel<4, true, true><<<aggBlocks, 256, 0, s0>>>(hA, b4, hB, n);

    // MLP head
    launch_gemm(s0, hB, wr + oF1, c1, hA, n, 128, 256, 128, MBIAS | MGELU | MRND);
    launch_gemm(s0, hA, wr + oF2, c2, hB, n, 256, 128, 256, MBIAS | MGELU | MRND);
    launch_gemm(s0, hB, wr + oF3, c3, out, n, 128, 64, 128, MBIAS);
}